// round 12
// baseline (speedup 1.0000x reference)
#include <cuda_runtime.h>
#include <cstdint>

#define N_NODES 100000
#define N_EDGES 1600000
#define NHID 64
#define NCLASS 40
#define SCAN_B 512
#define NBLK ((N_NODES + SCAN_B - 1) / SCAN_B)   // 196

// Scratch (static device globals — no allocation)
__device__ float g_agg[N_NODES * NHID];
__device__ float g_h[N_NODES * NHID];
__device__ int   g_deg[N_NODES];
__device__ int   g_off[N_NODES];
__device__ int   g_cur[N_NODES];
__device__ int   g_adj[N_EDGES];
__device__ int   g_bsum[NBLK];

// ---------------------------------------------------------------------------
// Edge-index dtype detection (int64 vs x64-disabled int32)
// ---------------------------------------------------------------------------
__device__ __forceinline__ bool ei_is64(const void* ei_raw) {
    const long long* e = (const long long*)ei_raw;
    return ((unsigned long long)e[0] < (1ULL << 32)) &&
           ((unsigned long long)e[1] < (1ULL << 32)) &&
           ((unsigned long long)e[2] < (1ULL << 32));
}
__device__ __forceinline__ int ei_at(const void* ei_raw, bool is64, int i) {
    return is64 ? (int)((const long long*)ei_raw)[i]
                : ((const int*)ei_raw)[i];
}

// ---------------------------------------------------------------------------
// CSR construction
// ---------------------------------------------------------------------------
__global__ void zero_deg_kernel(int* __restrict__ deg) {
    int i = blockIdx.x * blockDim.x + threadIdx.x;
    if (i < N_NODES) deg[i] = 0;
}

__global__ void hist_kernel(const void* __restrict__ ei, int* __restrict__ deg) {
    int e = blockIdx.x * blockDim.x + threadIdx.x;
    if (e >= N_EDGES) return;
    bool is64 = ei_is64(ei);
    int d = ei_at(ei, is64, N_EDGES + e);
    atomicAdd(&deg[d], 1);
}

// scan phase A: per-block sums of 512 deg entries
__global__ __launch_bounds__(SCAN_B) void scanA_kernel(
    const int* __restrict__ deg, int* __restrict__ bsum)
{
    __shared__ int s[SCAN_B];
    int t = threadIdx.x;
    int i = blockIdx.x * SCAN_B + t;
    s[t] = (i < N_NODES) ? deg[i] : 0;
    __syncthreads();
    #pragma unroll
    for (int k = SCAN_B / 2; k > 0; k >>= 1) {
        if (t < k) s[t] += s[t + k];
        __syncthreads();
    }
    if (t == 0) bsum[blockIdx.x] = s[0];
}

// scan phase B: exclusive scan of NBLK block sums — shfl warp scan + cross-warp
__global__ __launch_bounds__(256) void scanB_kernel(int* __restrict__ bsum) {
    __shared__ int wsum[8];
    int t = threadIdx.x;
    int lane = t & 31, w = t >> 5;
    int v = (t < NBLK) ? bsum[t] : 0;
    int incl = v;
    #pragma unroll
    for (int k = 1; k < 32; k <<= 1) {
        int u = __shfl_up_sync(0xffffffffu, incl, k);
        if (lane >= k) incl += u;
    }
    if (lane == 31) wsum[w] = incl;
    __syncthreads();
    if (w == 0) {
        int s = (lane < 8) ? wsum[lane] : 0;
        #pragma unroll
        for (int k = 1; k < 8; k <<= 1) {
            int u = __shfl_up_sync(0xffffffffu, s, k);
            if (lane >= k) s += u;
        }
        if (lane < 8) wsum[lane] = s;
    }
    __syncthreads();
    int base = (w > 0) ? wsum[w - 1] : 0;
    if (t < NBLK) bsum[t] = base + incl - v;    // exclusive
}

// scan phase C: per-block exclusive scan + carry -> off, cur
__global__ __launch_bounds__(SCAN_B) void scanC_kernel(
    const int* __restrict__ deg, const int* __restrict__ bsum,
    int* __restrict__ off, int* __restrict__ cur)
{
    __shared__ int sa[SCAN_B], sb[SCAN_B];
    int t = threadIdx.x;
    int i = blockIdx.x * SCAN_B + t;
    int v = (i < N_NODES) ? deg[i] : 0;
    sa[t] = v;
    __syncthreads();
    int* src = sa; int* dst = sb;
    #pragma unroll
    for (int k = 1; k < SCAN_B; k <<= 1) {
        dst[t] = (t >= k) ? src[t] + src[t - k] : src[t];
        __syncthreads();
        int* tmp = src; src = dst; dst = tmp;
    }
    if (i < N_NODES) {
        int excl = bsum[blockIdx.x] + src[t] - v;
        off[i] = excl;
        cur[i] = excl;
    }
}

__global__ void fill_kernel(const void* __restrict__ ei,
                            int* __restrict__ cur, int* __restrict__ adj) {
    int e = blockIdx.x * blockDim.x + threadIdx.x;
    if (e >= N_EDGES) return;
    bool is64 = ei_is64(ei);
    int s = ei_at(ei, is64, e);
    int d = ei_at(ei, is64, N_EDGES + e);
    int pos = atomicAdd(&cur[d], 1);
    adj[pos] = s;
}

// ---------------------------------------------------------------------------
// Pull aggregation: agg[i] = feat[i] + sum_j feat[adj[j]]
// 16 threads/node, one float4 each. Unroll-2 with dual accumulators and a
// depth-4 index pipeline -> 2 independent 256B gathers in flight per group.
// ---------------------------------------------------------------------------
__global__ __launch_bounds__(256) void aggregate_kernel(
    const float* __restrict__ feat, float* __restrict__ aggout,
    const int* __restrict__ off, const int* __restrict__ deg,
    const int* __restrict__ adj)
{
    int tid = blockIdx.x * blockDim.x + threadIdx.x;
    int node = tid >> 4;
    if (node >= N_NODES) return;
    int q = tid & 15;

    int o = off[node];
    int d = deg[node];
    const float4* f4 = (const float4*)feat;

    float4 accA = f4[(size_t)node * 16 + q];    // self term
    float4 accB = make_float4(0.f, 0.f, 0.f, 0.f);

    int idx[4];
    #pragma unroll
    for (int k = 0; k < 4; k++) idx[k] = (k < d) ? __ldg(adj + o + k) : 0;

    int j = 0;
    for (; j + 2 <= d; j += 2) {
        int n0 = idx[0], n1 = idx[1];
        idx[0] = idx[2]; idx[1] = idx[3];
        idx[2] = (j + 4 < d) ? __ldg(adj + o + j + 4) : 0;
        idx[3] = (j + 5 < d) ? __ldg(adj + o + j + 5) : 0;
        float4 v0 = f4[(size_t)n0 * 16 + q];
        float4 v1 = f4[(size_t)n1 * 16 + q];
        accA.x += v0.x; accA.y += v0.y; accA.z += v0.z; accA.w += v0.w;
        accB.x += v1.x; accB.y += v1.y; accB.z += v1.z; accB.w += v1.w;
    }
    if (j < d) {
        float4 v = f4[(size_t)idx[0] * 16 + q];
        accA.x += v.x; accA.y += v.y; accA.z += v.z; accA.w += v.w;
    }
    accA.x += accB.x; accA.y += accB.y; accA.z += accB.z; accA.w += accB.w;
    ((float4*)aggout)[(size_t)node * 16 + q] = accA;
}

// ---------------------------------------------------------------------------
// out = relu(A @ W + b); A-tile loads for step k+4 prefetched into registers
// before the FFMA block for step k (hides L2 latency behind compute).
// ---------------------------------------------------------------------------
__global__ __launch_bounds__(256) void gemm_relu_kernel(
    const float* __restrict__ A, const float* __restrict__ W,
    const float* __restrict__ b, float* __restrict__ out, int nrows)
{
    __shared__ __align__(16) float Ws[64 * 64];
    __shared__ float bs[64];
    int t = threadIdx.x;

    const float4* Wg = (const float4*)W;
    float4* Wsv = (float4*)Ws;
    #pragma unroll
    for (int i = 0; i < 4; i++) Wsv[t + i * 256] = Wg[t + i * 256];
    if (t < 64) bs[t] = b[t];
    __syncthreads();

    int cg = t >> 6;
    int rq = t & 63;
    int r0 = blockIdx.x * 256 + rq * 4;
    bool full = (r0 + 3 < nrows);

    float acc[4][16];
    #pragma unroll
    for (int rr = 0; rr < 4; rr++)
        #pragma unroll
        for (int c = 0; c < 16; c++) acc[rr][c] = 0.f;

    float4 cur[4], nxt[4];
    #pragma unroll
    for (int rr = 0; rr < 4; rr++) {
        int r = r0 + rr;
        cur[rr] = (full || r < nrows)
            ? *reinterpret_cast<const float4*>(A + (size_t)r * 64)
            : make_float4(0.f, 0.f, 0.f, 0.f);
    }

    #pragma unroll
    for (int k = 0; k < 64; k += 4) {
        if (k + 4 < 64) {
            #pragma unroll
            for (int rr = 0; rr < 4; rr++) {
                int r = r0 + rr;
                nxt[rr] = (full || r < nrows)
                    ? *reinterpret_cast<const float4*>(A + (size_t)r * 64 + k + 4)
                    : make_float4(0.f, 0.f, 0.f, 0.f);
            }
        }
        float xv[4][4];
        #pragma unroll
        for (int rr = 0; rr < 4; rr++) {
            xv[rr][0] = cur[rr].x; xv[rr][1] = cur[rr].y;
            xv[rr][2] = cur[rr].z; xv[rr][3] = cur[rr].w;
        }
        #pragma unroll
        for (int kk = 0; kk < 4; kk++) {
            const float4* wr = reinterpret_cast<const float4*>(Ws + (k + kk) * 64 + cg * 16);
            float w[16];
            #pragma unroll
            for (int j = 0; j < 4; j++) {
                float4 ww = wr[j];
                w[j*4+0] = ww.x; w[j*4+1] = ww.y; w[j*4+2] = ww.z; w[j*4+3] = ww.w;
            }
            #pragma unroll
            for (int rr = 0; rr < 4; rr++) {
                float a = xv[rr][kk];
                #pragma unroll
                for (int c = 0; c < 16; c++) acc[rr][c] += a * w[c];
            }
        }
        #pragma unroll
        for (int rr = 0; rr < 4; rr++) cur[rr] = nxt[rr];
    }

    #pragma unroll
    for (int rr = 0; rr < 4; rr++) {
        int r = r0 + rr;
        if (r < nrows) {
            float* op = out + (size_t)r * 64 + cg * 16;
            #pragma unroll
            for (int j = 0; j < 4; j++) {
                float4 o;
                o.x = fmaxf(acc[rr][j*4+0] + bs[cg*16 + j*4+0], 0.f);
                o.y = fmaxf(acc[rr][j*4+1] + bs[cg*16 + j*4+1], 0.f);
                o.z = fmaxf(acc[rr][j*4+2] + bs[cg*16 + j*4+2], 0.f);
                o.w = fmaxf(acc[rr][j*4+3] + bs[cg*16 + j*4+3], 0.f);
                *reinterpret_cast<float4*>(op + j * 4) = o;
            }
        }
    }
}

// ---------------------------------------------------------------------------
// out = log_softmax(A @ Wf + bf); 2 rows/thread, prefetched A, fused epilogue.
// ---------------------------------------------------------------------------
__global__ __launch_bounds__(256) void final_kernel(
    const float* __restrict__ A, const float* __restrict__ W,
    const float* __restrict__ b, float* __restrict__ out, int nrows)
{
    __shared__ __align__(16) float Ws[64 * NCLASS];
    __shared__ float bs[NCLASS];
    int t = threadIdx.x;
    for (int i = t; i < 64 * NCLASS / 4; i += 256)
        ((float4*)Ws)[i] = ((const float4*)W)[i];
    if (t < NCLASS) bs[t] = b[t];
    __syncthreads();

    int r0 = (blockIdx.x * 256 + t) * 2;

    float acc[2][NCLASS];
    #pragma unroll
    for (int rr = 0; rr < 2; rr++)
        #pragma unroll
        for (int c = 0; c < NCLASS; c++) acc[rr][c] = bs[c];

    float4 cur[2], nxt[2];
    #pragma unroll
    for (int rr = 0; rr < 2; rr++) {
        int r = r0 + rr;
        cur[rr] = (r < nrows)
            ? *reinterpret_cast<const float4*>(A + (size_t)r * 64)
            : make_float4(0.f, 0.f, 0.f, 0.f);
    }

    #pragma unroll
    for (int k = 0; k < 64; k += 4) {
        if (k + 4 < 64) {
            #pragma unroll
            for (int rr = 0; rr < 2; rr++) {
                int r = r0 + rr;
                nxt[rr] = (r < nrows)
                    ? *reinterpret_cast<const float4*>(A + (size_t)r * 64 + k + 4)
                    : make_float4(0.f, 0.f, 0.f, 0.f);
            }
        }
        float xv[2][4];
        #pragma unroll
        for (int rr = 0; rr < 2; rr++) {
            xv[rr][0] = cur[rr].x; xv[rr][1] = cur[rr].y;
            xv[rr][2] = cur[rr].z; xv[rr][3] = cur[rr].w;
        }
        #pragma unroll
        for (int kk = 0; kk < 4; kk++) {
            const float4* wr = reinterpret_cast<const float4*>(Ws + (k + kk) * NCLASS);
            #pragma unroll
            for (int c4 = 0; c4 < NCLASS / 4; c4++) {
                float4 ww = wr[c4];
                #pragma unroll
                for (int rr = 0; rr < 2; rr++) {
                    float a = xv[rr][kk];
                    acc[rr][c4*4+0] += a * ww.x;
                    acc[rr][c4*4+1] += a * ww.y;
                    acc[rr][c4*4+2] += a * ww.z;
                    acc[rr][c4*4+3] += a * ww.w;
                }
            }
        }
        #pragma unroll
        for (int rr = 0; rr < 2; rr++) cur[rr] = nxt[rr];
    }

    #pragma unroll
    for (int rr = 0; rr < 2; rr++) {
        int r = r0 + rr;
        if (r >= nrows) continue;
        float m = acc[rr][0];
        #pragma unroll
        for (int c = 1; c < NCLASS; c++) m = fmaxf(m, acc[rr][c]);
        float s = 0.f;
        #pragma unroll
        for (int c = 0; c < NCLASS; c++) s += __expf(acc[rr][c] - m);
        float lse = m + __logf(s);
        float* op = out + (size_t)r * NCLASS;
        #pragma unroll
        for (int c4 = 0; c4 < NCLASS / 4; c4++) {
            float4 o;
            o.x = acc[rr][c4*4+0] - lse;
            o.y = acc[rr][c4*4+1] - lse;
            o.z = acc[rr][c4*4+2] - lse;
            o.w = acc[rr][c4*4+3] - lse;
            *reinterpret_cast<float4*>(op + c4 * 4) = o;
        }
    }
}

// ---------------------------------------------------------------------------
extern "C" void kernel_launch(void* const* d_in, const int* in_sizes, int n_in,
                              void* d_out, int out_size) {
    const float* x  = (const float*)d_in[0];
    const void*  ei = d_in[1];
    const float* W1 = (const float*)d_in[2];
    const float* b1 = (const float*)d_in[3];
    const float* W2 = (const float*)d_in[4];
    const float* b2 = (const float*)d_in[5];
    const float* Wf = (const float*)d_in[6];
    const float* bf = (const float*)d_in[7];
    float* out = (float*)d_out;

    float *agg, *h;
    int *deg, *off, *cur, *adj, *bsum;
    cudaGetSymbolAddress((void**)&agg,  g_agg);
    cudaGetSymbolAddress((void**)&h,    g_h);
    cudaGetSymbolAddress((void**)&deg,  g_deg);
    cudaGetSymbolAddress((void**)&off,  g_off);
    cudaGetSymbolAddress((void**)&cur,  g_cur);
    cudaGetSymbolAddress((void**)&adj,  g_adj);
    cudaGetSymbolAddress((void**)&bsum, g_bsum);

    const int edge_blocks = (N_EDGES + 255) / 256;
    const int node_blocks = (N_NODES + 255) / 256;
    const int agg_blocks  = (N_NODES * 16 + 255) / 256;
    const int gemm_blocks = (N_NODES + 255) / 256;
    const int fin_blocks  = (N_NODES + 511) / 512;

    // ---- CSR build (once per call, reused by both layers) ----
    zero_deg_kernel<<<node_blocks, 256>>>(deg);
    hist_kernel<<<edge_blocks, 256>>>(ei, deg);
    scanA_kernel<<<NBLK, SCAN_B>>>(deg, bsum);
    scanB_kernel<<<1, 256>>>(bsum);
    scanC_kernel<<<NBLK, SCAN_B>>>(deg, bsum, off, cur);
    fill_kernel<<<edge_blocks, 256>>>(ei, cur, adj);

    // ---- Layer 1: agg = x + sum_nbr x ; h = relu(agg @ W1 + b1) ----
    aggregate_kernel<<<agg_blocks, 256>>>(x, agg, off, deg, adj);
    gemm_relu_kernel<<<gemm_blocks, 256>>>(agg, W1, b1, h, N_NODES);

    // ---- Layer 2 ----
    aggregate_kernel<<<agg_blocks, 256>>>(h, agg, off, deg, adj);
    gemm_relu_kernel<<<gemm_blocks, 256>>>(agg, W2, b2, h, N_NODES);

    // ---- Classifier + fused log_softmax ----
    final_kernel<<<fin_blocks, 256>>>(h, Wf, bf, out, N_NODES);
}

// round 13
// speedup vs baseline: 1.0712x; 1.0712x over previous
#include <cuda_runtime.h>
#include <cstdint>

#define N_NODES 100000
#define N_EDGES 1600000
#define NHID 64
#define NCLASS 40
#define SCAN_B 512
#define NBLK ((N_NODES + SCAN_B - 1) / SCAN_B)   // 196

// Scratch (static device globals — no allocation)
__device__ float g_agg[N_NODES * NHID];
__device__ float g_h[N_NODES * NHID];
__device__ int   g_deg[N_NODES];
__device__ int   g_off[N_NODES];
__device__ int   g_cur[N_NODES];
__device__ int   g_adj[N_EDGES];
__device__ int   g_bsum[NBLK];

// ---------------------------------------------------------------------------
// Edge-index dtype detection (int64 vs x64-disabled int32)
// ---------------------------------------------------------------------------
__device__ __forceinline__ bool ei_is64(const void* ei_raw) {
    const long long* e = (const long long*)ei_raw;
    return ((unsigned long long)e[0] < (1ULL << 32)) &&
           ((unsigned long long)e[1] < (1ULL << 32)) &&
           ((unsigned long long)e[2] < (1ULL << 32));
}
__device__ __forceinline__ int ei_at(const void* ei_raw, bool is64, int i) {
    return is64 ? (int)((const long long*)ei_raw)[i]
                : ((const int*)ei_raw)[i];
}

// ---------------------------------------------------------------------------
// CSR construction
// ---------------------------------------------------------------------------
__global__ void hist_kernel(const void* __restrict__ ei, int* __restrict__ deg) {
    int e = blockIdx.x * blockDim.x + threadIdx.x;
    if (e >= N_EDGES) return;
    bool is64 = ei_is64(ei);
    int d = ei_at(ei, is64, N_EDGES + e);
    atomicAdd(&deg[d], 1);
}

// scan phase A: per-block sums of 512 deg entries
__global__ __launch_bounds__(SCAN_B) void scanA_kernel(
    const int* __restrict__ deg, int* __restrict__ bsum)
{
    __shared__ int s[SCAN_B];
    int t = threadIdx.x;
    int i = blockIdx.x * SCAN_B + t;
    s[t] = (i < N_NODES) ? deg[i] : 0;
    __syncthreads();
    #pragma unroll
    for (int k = SCAN_B / 2; k > 0; k >>= 1) {
        if (t < k) s[t] += s[t + k];
        __syncthreads();
    }
    if (t == 0) bsum[blockIdx.x] = s[0];
}

// scan phase C (fused base): each block reduces bsum[j], j < blockIdx.x, to get
// its exclusive carry, then does a Hillis-Steele scan of its own 512 degs.
// This eliminates the former grid=1 scanB kernel (~4.4us launch floor).
__global__ __launch_bounds__(SCAN_B) void scanC_kernel(
    const int* __restrict__ deg, const int* __restrict__ bsum,
    int* __restrict__ off, int* __restrict__ cur)
{
    __shared__ int sa[SCAN_B], sb[SCAN_B];
    int t = threadIdx.x;

    // --- exclusive base = sum of bsum[0..blockIdx.x) ---
    sa[t] = (t < NBLK && t < blockIdx.x) ? bsum[t] : 0;
    __syncthreads();
    #pragma unroll
    for (int k = SCAN_B / 2; k > 0; k >>= 1) {
        if (t < k) sa[t] += sa[t + k];
        __syncthreads();
    }
    int base = sa[0];
    __syncthreads();

    // --- intra-block inclusive scan of deg ---
    int i = blockIdx.x * SCAN_B + t;
    int v = (i < N_NODES) ? deg[i] : 0;
    sa[t] = v;
    __syncthreads();
    int* src = sa; int* dst = sb;
    #pragma unroll
    for (int k = 1; k < SCAN_B; k <<= 1) {
        dst[t] = (t >= k) ? src[t] + src[t - k] : src[t];
        __syncthreads();
        int* tmp = src; src = dst; dst = tmp;
    }
    if (i < N_NODES) {
        int excl = base + src[t] - v;
        off[i] = excl;
        cur[i] = excl;
    }
}

__global__ void fill_kernel(const void* __restrict__ ei,
                            int* __restrict__ cur, int* __restrict__ adj) {
    int e = blockIdx.x * blockDim.x + threadIdx.x;
    if (e >= N_EDGES) return;
    bool is64 = ei_is64(ei);
    int s = ei_at(ei, is64, e);
    int d = ei_at(ei, is64, N_EDGES + e);
    int pos = atomicAdd(&cur[d], 1);
    adj[pos] = s;
}

// ---------------------------------------------------------------------------
// Pull aggregation: agg[i] = feat[i] + sum_j feat[adj[j]]  (R11 version)
// 16 threads/node, one float4 each; depth-2 index prefetch.
// ---------------------------------------------------------------------------
__global__ __launch_bounds__(256) void aggregate_kernel(
    const float* __restrict__ feat, float* __restrict__ aggout,
    const int* __restrict__ off, const int* __restrict__ deg,
    const int* __restrict__ adj)
{
    int tid = blockIdx.x * blockDim.x + threadIdx.x;
    int node = tid >> 4;
    if (node >= N_NODES) return;
    int q = tid & 15;

    int o = off[node];
    int d = deg[node];

    float4 acc = ((const float4*)(feat + (size_t)node * NHID))[q];   // self term

    int i0 = (d > 0) ? __ldg(adj + o) : 0;
    int i1 = (d > 1) ? __ldg(adj + o + 1) : 0;
    for (int j = 0; j < d; j++) {
        int inext = (j + 2 < d) ? __ldg(adj + o + j + 2) : 0;
        float4 v = ((const float4*)(feat + (size_t)i0 * NHID))[q];
        acc.x += v.x; acc.y += v.y; acc.z += v.z; acc.w += v.w;
        i0 = i1; i1 = inext;
    }
    ((float4*)(aggout + (size_t)node * NHID))[q] = acc;
}

// ---------------------------------------------------------------------------
// out = relu(A @ W + b)   (R11 scalar-FFMA version — known good)
// ---------------------------------------------------------------------------
__global__ __launch_bounds__(256) void gemm_relu_kernel(
    const float* __restrict__ A, const float* __restrict__ W,
    const float* __restrict__ b, float* __restrict__ out, int nrows)
{
    __shared__ __align__(16) float Ws[64 * 64];
    __shared__ float bs[64];
    int t = threadIdx.x;

    const float4* Wg = (const float4*)W;
    float4* Wsv = (float4*)Ws;
    #pragma unroll
    for (int i = 0; i < 4; i++) Wsv[t + i * 256] = Wg[t + i * 256];
    if (t < 64) bs[t] = b[t];
    __syncthreads();

    int cg = t >> 6;
    int rq = t & 63;
    int r0 = blockIdx.x * 256 + rq * 4;

    float acc[4][16];
    #pragma unroll
    for (int rr = 0; rr < 4; rr++)
        #pragma unroll
        for (int c = 0; c < 16; c++) acc[rr][c] = 0.f;

    for (int k = 0; k < 64; k += 4) {
        float xv[4][4];
        #pragma unroll
        for (int rr = 0; rr < 4; rr++) {
            int r = r0 + rr;
            float4 v = (r < nrows)
                ? *reinterpret_cast<const float4*>(A + (size_t)r * 64 + k)
                : make_float4(0.f, 0.f, 0.f, 0.f);
            xv[rr][0] = v.x; xv[rr][1] = v.y; xv[rr][2] = v.z; xv[rr][3] = v.w;
        }
        #pragma unroll
        for (int kk = 0; kk < 4; kk++) {
            const float4* wr = reinterpret_cast<const float4*>(Ws + (k + kk) * 64 + cg * 16);
            float w[16];
            #pragma unroll
            for (int j = 0; j < 4; j++) {
                float4 ww = wr[j];
                w[j*4+0] = ww.x; w[j*4+1] = ww.y; w[j*4+2] = ww.z; w[j*4+3] = ww.w;
            }
            #pragma unroll
            for (int rr = 0; rr < 4; rr++) {
                float a = xv[rr][kk];
                #pragma unroll
                for (int c = 0; c < 16; c++) acc[rr][c] += a * w[c];
            }
        }
    }

    #pragma unroll
    for (int rr = 0; rr < 4; rr++) {
        int r = r0 + rr;
        if (r < nrows) {
            float* op = out + (size_t)r * 64 + cg * 16;
            #pragma unroll
            for (int j = 0; j < 4; j++) {
                float4 o;
                o.x = fmaxf(acc[rr][j*4+0] + bs[cg*16 + j*4+0], 0.f);
                o.y = fmaxf(acc[rr][j*4+1] + bs[cg*16 + j*4+1], 0.f);
                o.z = fmaxf(acc[rr][j*4+2] + bs[cg*16 + j*4+2], 0.f);
                o.w = fmaxf(acc[rr][j*4+3] + bs[cg*16 + j*4+3], 0.f);
                *reinterpret_cast<float4*>(op + j * 4) = o;
            }
        }
    }
}

// ---------------------------------------------------------------------------
// out = log_softmax(A @ Wf + bf)   (R11 version)
// ---------------------------------------------------------------------------
__global__ __launch_bounds__(256) void final_kernel(
    const float* __restrict__ A, const float* __restrict__ W,
    const float* __restrict__ b, float* __restrict__ out, int nrows)
{
    __shared__ __align__(16) float Ws[64 * NCLASS];
    __shared__ float bs[NCLASS];
    int t = threadIdx.x;
    for (int i = t; i < 64 * NCLASS / 4; i += 256)
        ((float4*)Ws)[i] = ((const float4*)W)[i];
    if (t < NCLASS) bs[t] = b[t];
    __syncthreads();

    int r0 = (blockIdx.x * 256 + t) * 2;

    float acc[2][NCLASS];
    #pragma unroll
    for (int rr = 0; rr < 2; rr++)
        #pragma unroll
        for (int c = 0; c < NCLASS; c++) acc[rr][c] = bs[c];

    for (int k = 0; k < 64; k += 4) {
        float xv[2][4];
        #pragma unroll
        for (int rr = 0; rr < 2; rr++) {
            int r = r0 + rr;
            float4 v = (r < nrows)
                ? *reinterpret_cast<const float4*>(A + (size_t)r * 64 + k)
                : make_float4(0.f, 0.f, 0.f, 0.f);
            xv[rr][0] = v.x; xv[rr][1] = v.y; xv[rr][2] = v.z; xv[rr][3] = v.w;
        }
        #pragma unroll
        for (int kk = 0; kk < 4; kk++) {
            const float4* wr = reinterpret_cast<const float4*>(Ws + (k + kk) * NCLASS);
            #pragma unroll
            for (int c4 = 0; c4 < NCLASS / 4; c4++) {
                float4 ww = wr[c4];
                #pragma unroll
                for (int rr = 0; rr < 2; rr++) {
                    float a = xv[rr][kk];
                    acc[rr][c4*4+0] += a * ww.x;
                    acc[rr][c4*4+1] += a * ww.y;
                    acc[rr][c4*4+2] += a * ww.z;
                    acc[rr][c4*4+3] += a * ww.w;
                }
            }
        }
    }

    #pragma unroll
    for (int rr = 0; rr < 2; rr++) {
        int r = r0 + rr;
        if (r >= nrows) continue;
        float m = acc[rr][0];
        #pragma unroll
        for (int c = 1; c < NCLASS; c++) m = fmaxf(m, acc[rr][c]);
        float s = 0.f;
        #pragma unroll
        for (int c = 0; c < NCLASS; c++) s += __expf(acc[rr][c] - m);
        float lse = m + __logf(s);
        float* op = out + (size_t)r * NCLASS;
        #pragma unroll
        for (int c4 = 0; c4 < NCLASS / 4; c4++) {
            float4 o;
            o.x = acc[rr][c4*4+0] - lse;
            o.y = acc[rr][c4*4+1] - lse;
            o.z = acc[rr][c4*4+2] - lse;
            o.w = acc[rr][c4*4+3] - lse;
            *reinterpret_cast<float4*>(op + c4 * 4) = o;
        }
    }
}

// ---------------------------------------------------------------------------
extern "C" void kernel_launch(void* const* d_in, const int* in_sizes, int n_in,
                              void* d_out, int out_size) {
    const float* x  = (const float*)d_in[0];
    const void*  ei = d_in[1];
    const float* W1 = (const float*)d_in[2];
    const float* b1 = (const float*)d_in[3];
    const float* W2 = (const float*)d_in[4];
    const float* b2 = (const float*)d_in[5];
    const float* Wf = (const float*)d_in[6];
    const float* bf = (const float*)d_in[7];
    float* out = (float*)d_out;

    float *agg, *h;
    int *deg, *off, *cur, *adj, *bsum;
    cudaGetSymbolAddress((void**)&agg,  g_agg);
    cudaGetSymbolAddress((void**)&h,    g_h);
    cudaGetSymbolAddress((void**)&deg,  g_deg);
    cudaGetSymbolAddress((void**)&off,  g_off);
    cudaGetSymbolAddress((void**)&cur,  g_cur);
    cudaGetSymbolAddress((void**)&adj,  g_adj);
    cudaGetSymbolAddress((void**)&bsum, g_bsum);

    const int edge_blocks = (N_EDGES + 255) / 256;
    const int agg_blocks  = (N_NODES * 16 + 255) / 256;
    const int gemm_blocks = (N_NODES + 255) / 256;
    const int fin_blocks  = (N_NODES + 511) / 512;

    // ---- CSR build (once per call, reused by both layers) ----
    cudaMemsetAsync(deg, 0, N_NODES * sizeof(int));
    hist_kernel<<<edge_blocks, 256>>>(ei, deg);
    scanA_kernel<<<NBLK, SCAN_B>>>(deg, bsum);
    scanC_kernel<<<NBLK, SCAN_B>>>(deg, bsum, off, cur);
    fill_kernel<<<edge_blocks, 256>>>(ei, cur, adj);

    // ---- Layer 1: agg = x + sum_nbr x ; h = relu(agg @ W1 + b1) ----
    aggregate_kernel<<<agg_blocks, 256>>>(x, agg, off, deg, adj);
    gemm_relu_kernel<<<gemm_blocks, 256>>>(agg, W1, b1, h, N_NODES);

    // ---- Layer 2 ----
    aggregate_kernel<<<agg_blocks, 256>>>(h, agg, off, deg, adj);
    gemm_relu_kernel<<<gemm_blocks, 256>>>(agg, W2, b2, h, N_NODES);

    // ---- Classifier + fused log_softmax ----
    final_kernel<<<fin_blocks, 256>>>(h, Wf, bf, out, N_NODES);
}